// round 6
// baseline (speedup 1.0000x reference)
#include <cuda_runtime.h>
#include <cuda_bf16.h>
#include <math.h>

// Problem shapes (fixed for this dataset)
#define KDIM 32
#define DDIM 32
#define N_I 5000
#define N_J 5000
#define M_I 2500
#define M_J 2500
#define N_EDGES 200000
#define EPSV 1e-6f
#define C0 (32.0f * EPSV * EPSV)

#define TPB 256
#define BT 128                        // pair tile edge
#define NTI ((M_I + BT - 1) / BT)     // 20
#define NTJ ((M_J + BT - 1) / BT)     // 20
#define NPAIR (NTI * NTJ)             // 400
#define EDGE_PER_BLK 2048
#define NEDGE_BLKS ((N_EDGES + EDGE_PER_BLK - 1) / EDGE_PER_BLK)  // 98
#define K3_BLOCKS (NPAIR + NEDGE_BLKS)                            // 498

#define SOFT_BLOCKS ((N_I + N_J + TPB - 1) / TPB)   // 40
#define STATS_BLOCKS 20
#define K1_BLOCKS (SOFT_BLOCKS + STATS_BLOCKS)      // 60

// ---------------- scratch (static device globals; zero-initialized) ----------
// INVARIANT: g_T, g_s, g_mat, g_links, g_done are zero at kernel_launch entry.
// They start zero (module load) and K3's final block re-zeroes them each call.
__device__ float g_SZi[KDIM * N_I];      // softmax(Z_i) (k, n_i)
__device__ float g_SZj[KDIM * N_J];      // softmax(Z_j) (k, n_j)
__device__ float g_T[KDIM * KDIM];       // T[a][b] = sum_m Z[a,m] Z[b,m] G[m,b]
__device__ float g_s[KDIM];              // s[b]
__device__ float g_Xi[N_I * DDIM];       // latent rows (128B each)
__device__ float g_qi[N_I];              // ||x||^2 + 2 eps sum(x)
__device__ float g_Xj[N_J * DDIM];
__device__ float g_qj[N_J];              // ||x||^2 - 2 eps sum(x)
__device__ double g_mat;
__device__ double g_links;
__device__ unsigned int g_done;

// ---------------- helpers ------------------------------------------------------
__device__ __forceinline__ float block_reduce(float v, float* red) {
#pragma unroll
    for (int o = 16; o; o >>= 1) v += __shfl_down_sync(0xffffffffu, v, o);
    int t = threadIdx.x;
    if ((t & 31) == 0) red[t >> 5] = v;
    __syncthreads();
    float s = 0.f;
    if (t == 0) {
#pragma unroll
        for (int i = 0; i < TPB / 32; i++) s += red[i];
    }
    return s;          // valid on t==0 only
}

// ---------------- K1: full softmax + gate statistics (independent halves) -----
__global__ void __launch_bounds__(TPB) k1_soft_stats(
    const float* __restrict__ Z_i, const float* __restrict__ Z_j,
    const float* __restrict__ Gate,
    const int* __restrict__ si, const int* __restrict__ sj)
{
    const int bid = blockIdx.x;
    const int tid = threadIdx.x;

    if (bid < SOFT_BLOCKS) {
        // ---- full column softmax of Z_i / Z_j (consumed by K2) ----
        int c = bid * TPB + tid;
        if (c >= N_I + N_J) return;
        const float* src; float* dst; int n, cc;
        if (c < N_I) { src = Z_i; dst = g_SZi; n = N_I; cc = c; }
        else         { src = Z_j; dst = g_SZj; n = N_J; cc = c - N_I; }
        float v[KDIM];
        float mx = -1e30f;
#pragma unroll
        for (int a = 0; a < KDIM; a++) { v[a] = src[a * n + cc]; mx = fmaxf(mx, v[a]); }
        float sum = 0.f;
#pragma unroll
        for (int a = 0; a < KDIM; a++) { v[a] = __expf(v[a] - mx); sum += v[a]; }
        float inv = 1.f / sum;
#pragma unroll
        for (int a = 0; a < KDIM; a++) dst[a * n + cc] = v[a] * inv;
    } else {
        // ---- gate statistics s[b], T[a][b]; softmax recomputed inline ----
        int sb = bid - SOFT_BLOCKS;
        int gwarp = (sb * TPB + tid) >> 5;
        int lane = tid & 31;
        int nwarps = (STATS_BLOCKS * TPB) >> 5;

        float sacc = 0.f;
        float tacc[KDIM];
#pragma unroll
        for (int a = 0; a < KDIM; a++) tacc[a] = 0.f;

        for (int m = gwarp; m < M_I + M_J; m += nwarps) {
            int idx; const float* Zsrc; int n;
            if (m < M_I) { idx = si[m]; Zsrc = Z_i; n = N_I; }
            else         { idx = sj[m - M_I]; Zsrc = Z_j; n = N_J; }
            // inline softmax over the k axis for this column
            float zv = Zsrc[lane * n + idx];
            float mx = zv;
#pragma unroll
            for (int o = 16; o; o >>= 1) mx = fmaxf(mx, __shfl_xor_sync(0xffffffffu, mx, o));
            float e = __expf(zv - mx);
            float es = e;
#pragma unroll
            for (int o = 16; o; o >>= 1) es += __shfl_xor_sync(0xffffffffu, es, o);
            float z = e / es;

            float gt = Gate[idx * KDIM + lane];  // faithful: j-side indexes Gate w/o offset
            float g = 1.f / (1.f + __expf(-gt));
            float w = z * g;
            sacc += w;
#pragma unroll
            for (int a = 0; a < KDIM; a++) {
                float za = __shfl_sync(0xffffffffu, z, a);
                tacc[a] = fmaf(za, w, tacc[a]);
            }
        }
        atomicAdd(&g_s[lane], sacc);
#pragma unroll
        for (int a = 0; a < KDIM; a++) atomicAdd(&g_T[a * KDIM + lane], tacc[a]);
    }
}

// ---------------- K2: AZC (redundant per block) + per-node latent rows --------
__global__ void __launch_bounds__(TPB) k2_latent(const float* __restrict__ A) {
    __shared__ float az[DDIM][KDIM];
    const int tid = threadIdx.x;

    for (int e = tid; e < DDIM * KDIM; e += TPB) {
        int dd = e >> 5, b = e & 31;
        float acc = 0.f;
#pragma unroll
        for (int a = 0; a < KDIM; a++) acc = fmaf(A[dd * KDIM + a], g_T[a * KDIM + b], acc);
        az[dd][b] = acc / g_s[b];
    }
    __syncthreads();

    int c = blockIdx.x * TPB + tid;
    if (c >= N_I + N_J) return;
    const float* SZ; float* X; float* q; int n, cc, side;
    if (c < N_I) { SZ = g_SZi; X = g_Xi; q = g_qi; n = N_I; cc = c; side = 0; }
    else         { SZ = g_SZj; X = g_Xj; q = g_qj; n = N_J; cc = c - N_I; side = 1; }

    float x[DDIM];
#pragma unroll
    for (int dd = 0; dd < DDIM; dd++) x[dd] = 0.f;
#pragma unroll
    for (int a = 0; a < KDIM; a++) {
        float z = SZ[a * n + cc];
#pragma unroll
        for (int dd = 0; dd < DDIM; dd++) x[dd] = fmaf(az[dd][a], z, x[dd]);
    }
    float s2 = 0.f, s1 = 0.f;
    float4* o4 = (float4*)&X[cc * DDIM];
#pragma unroll
    for (int w = 0; w < DDIM / 4; w++) {
        float4 v4 = make_float4(x[4 * w], x[4 * w + 1], x[4 * w + 2], x[4 * w + 3]);
        s2 = fmaf(v4.x, v4.x, fmaf(v4.y, v4.y, fmaf(v4.z, v4.z, fmaf(v4.w, v4.w, s2))));
        s1 += v4.x + v4.y + v4.z + v4.w;
        o4[w] = v4;
    }
    q[cc] = side == 0 ? (s2 + 2.f * EPSV * s1) : (s2 - 2.f * EPSV * s1);
}

// ---------------- K3: pair tiles + edge chunks + final + cleanup --------------
__global__ void __launch_bounds__(TPB, 2) k3_pair_edges(
    const float* __restrict__ beta, const float* __restrict__ gamma,
    const int* __restrict__ si, const int* __restrict__ sj,
    const int* __restrict__ spi, const int* __restrict__ spj,
    float* __restrict__ out)
{
    __shared__ float s_As[KDIM][BT + 4];   // 528B row base stays 16B aligned
    __shared__ float s_Bs[KDIM][BT + 4];
    __shared__ float s_qa[BT], s_ba[BT], s_qb[BT], s_gb[BT];
    __shared__ float s_red[TPB / 32];

    const int tid = threadIdx.x;
    const int item = blockIdx.x;

    if (item < NPAIR) {
        // ---- dense pairwise exp-distance tile (BT x BT) ----
        int ti = item / NTJ, tj = item - ti * NTJ;
        int i0 = ti * BT, j0 = tj * BT;

        for (int e = tid; e < BT * KDIM; e += TPB) {
            int r = e >> 5, kk = e & 31;           // lanes sweep kk -> coalesced row reads
            int rg = i0 + r;
            float v = 0.f;
            if (rg < M_I) v = g_Xi[si[rg] * DDIM + kk];
            s_As[kk][r] = v;
            rg = j0 + r;
            v = 0.f;
            if (rg < M_J) v = g_Xj[sj[rg] * DDIM + kk];
            s_Bs[kk][r] = v;
        }
        if (tid < BT) {
            int rg = i0 + tid;
            if (rg < M_I) { int idx = si[rg]; s_qa[tid] = g_qi[idx]; s_ba[tid] = beta[idx]; }
            else          { s_qa[tid] = 1e30f; s_ba[tid] = 0.f; }
        } else {
            int p = tid - BT;
            int rg = j0 + p;
            if (rg < M_J) { int idx = sj[rg]; s_qb[p] = g_qj[idx]; s_gb[p] = gamma[idx]; }
            else          { s_qb[p] = 1e30f; s_gb[p] = 0.f; }
        }
        __syncthreads();

        const int tx = tid & 15, ty = tid >> 4;
        const int r0 = ty * 8, c0 = tx * 8;

        unsigned long long acc[8][4];
#pragma unroll
        for (int r = 0; r < 8; r++)
#pragma unroll
            for (int c = 0; c < 4; c++) acc[r][c] = 0ULL;

#pragma unroll
        for (int kk = 0; kk < KDIM; kk++) {
            float4 a0 = *(const float4*)&s_As[kk][r0];
            float4 a1 = *(const float4*)&s_As[kk][r0 + 4];
            ulonglong2 b0 = *(const ulonglong2*)&s_Bs[kk][c0];
            ulonglong2 b1 = *(const ulonglong2*)&s_Bs[kk][c0 + 4];
            float av[8] = {a0.x, a0.y, a0.z, a0.w, a1.x, a1.y, a1.z, a1.w};
            unsigned long long bp[4] = {b0.x, b0.y, b1.x, b1.y};
#pragma unroll
            for (int r = 0; r < 8; r++) {
                unsigned long long ad;
                asm("mov.b64 %0, {%1, %1};" : "=l"(ad) : "f"(av[r]));
#pragma unroll
                for (int c = 0; c < 4; c++) {
                    asm("fma.rn.f32x2 %0, %1, %2, %0;" : "+l"(acc[r][c]) : "l"(ad), "l"(bp[c]));
                }
            }
        }

        float sum = 0.f;
#pragma unroll
        for (int r = 0; r < 8; r++) {
            float qa = s_qa[r0 + r];
            float ba = s_ba[r0 + r];
#pragma unroll
            for (int c = 0; c < 4; c++) {
                float dlo, dhi;
                asm("mov.b64 {%0, %1}, %2;" : "=f"(dlo), "=f"(dhi) : "l"(acc[r][c]));
                int cl = c0 + 2 * c;
                float d2a = qa + s_qb[cl] - 2.f * dlo + C0;
                float d2b = qa + s_qb[cl + 1] - 2.f * dhi + C0;
                d2a = fmaxf(d2a, 0.f);
                d2b = fmaxf(d2b, 0.f);
                sum += __expf(ba + s_gb[cl] - sqrtf(d2a));
                sum += __expf(ba + s_gb[cl + 1] - sqrtf(d2b));
            }
        }
        float bs = block_reduce(sum, s_red);
        if (tid == 0) atomicAdd(&g_mat, (double)bs);
    } else {
        // ---- sparse edge chunk ----
        int base = (item - NPAIR) * EDGE_PER_BLK;
        float sum = 0.f;
#pragma unroll
        for (int l = 0; l < EDGE_PER_BLK / TPB; l++) {
            int e = base + l * TPB + tid;
            if (e < N_EDGES) {
                int ii = spi[e];
                int jj = spj[e];
                const float4* xa = (const float4*)&g_Xi[ii * DDIM];
                const float4* xb = (const float4*)&g_Xj[jj * DDIM];
                float dot = 0.f;
#pragma unroll
                for (int w = 0; w < DDIM / 4; w++) {
                    float4 a = xa[w], b = xb[w];
                    dot = fmaf(a.x, b.x, dot);
                    dot = fmaf(a.y, b.y, dot);
                    dot = fmaf(a.z, b.z, dot);
                    dot = fmaf(a.w, b.w, dot);
                }
                float d2 = g_qi[ii] + g_qj[jj] - 2.f * dot + C0;
                d2 = fmaxf(d2, 0.f);
                sum += beta[ii] + gamma[jj] - sqrtf(d2);
            }
        }
        float bs = block_reduce(sum, s_red);
        if (tid == 0) atomicAdd(&g_links, (double)bs);
    }

    // ---- last-block-done: final scalar + reset accumulators for next replay ----
    __syncthreads();
    __threadfence();
    __shared__ unsigned int s_last;
    if (tid == 0) s_last = atomicAdd(&g_done, 1u);
    __syncthreads();
    if (s_last == K3_BLOCKS - 1) {
        if (tid == 0) {
            double m = atomicAdd(&g_mat, 0.0);      // acquire-ish read after fence chain
            double l = atomicAdd(&g_links, 0.0);
            out[0] = (float)(l - m);
            g_mat = 0.0;
            g_links = 0.0;
            g_done = 0u;
            g_s[0] = 0.f;
        }
        // re-zero stats accumulators so next replay starts clean
        for (int e = tid; e < KDIM * KDIM; e += TPB) g_T[e] = 0.f;
        if (tid > 0 && tid < KDIM) g_s[tid] = 0.f;
    }
}

// ---------------- launcher -----------------------------------------------------
extern "C" void kernel_launch(void* const* d_in, const int* in_sizes, int n_in,
                              void* d_out, int out_size) {
    const float* beta  = (const float*)d_in[0];
    const float* gamma = (const float*)d_in[1];
    const float* A     = (const float*)d_in[2];
    const float* Z_i   = (const float*)d_in[3];
    const float* Z_j   = (const float*)d_in[4];
    const float* Gate  = (const float*)d_in[5];
    const int* si      = (const int*)d_in[6];
    const int* sj      = (const int*)d_in[7];
    const int* spi     = (const int*)d_in[8];
    const int* spj     = (const int*)d_in[9];
    float* out = (float*)d_out;

    k1_soft_stats<<<K1_BLOCKS, TPB>>>(Z_i, Z_j, Gate, si, sj);
    k2_latent<<<(N_I + N_J + TPB - 1) / TPB, TPB>>>(A);
    k3_pair_edges<<<K3_BLOCKS, TPB>>>(beta, gamma, si, sj, spi, spj, out);
}

// round 7
// speedup vs baseline: 1.0038x; 1.0038x over previous
#include <cuda_runtime.h>
#include <cuda_bf16.h>
#include <math.h>

// Problem shapes (fixed for this dataset)
#define KDIM 32
#define DDIM 32
#define N_I 5000
#define N_J 5000
#define M_I 2500
#define M_J 2500
#define N_EDGES 200000
#define EPSV 1e-6f
#define C0 (32.0f * EPSV * EPSV)

#define TPB 256
#define BT 128                        // pair tile edge
#define NTI ((M_I + BT - 1) / BT)     // 20
#define NTJ ((M_J + BT - 1) / BT)     // 20
#define NPAIR (NTI * NTJ)             // 400
#define EDGE_PER_BLK 2048
#define NEDGE_BLKS ((N_EDGES + EDGE_PER_BLK - 1) / EDGE_PER_BLK)  // 98
#define K3_BLOCKS (NPAIR + NEDGE_BLKS)                            // 498

#define SOFT_BLOCKS ((N_I + N_J + TPB - 1) / TPB)   // 40
#define STATS_BLOCKS 20
#define K1_BLOCKS (SOFT_BLOCKS + STATS_BLOCKS)      // 60

// ---------------- scratch (static device globals; zero-initialized) ----------
// INVARIANT: g_T, g_s, g_mat, g_links, g_done are zero at kernel_launch entry.
// They start zero (module load) and K3's final block re-zeroes them each call.
__device__ float g_SZi[KDIM * N_I];      // softmax(Z_i) (k, n_i)
__device__ float g_SZj[KDIM * N_J];      // softmax(Z_j) (k, n_j)
__device__ float g_T[KDIM * KDIM];       // T[a][b] = sum_m Z[a,m] Z[b,m] G[m,b]
__device__ float g_s[KDIM];              // s[b]
__device__ float g_Xi[N_I * DDIM];       // latent rows (128B each)
__device__ float g_qi[N_I];              // ||x||^2 + 2 eps sum(x)
__device__ float g_Xj[N_J * DDIM];
__device__ float g_qj[N_J];              // ||x||^2 - 2 eps sum(x)
__device__ double g_mat;
__device__ double g_links;
__device__ unsigned int g_done;

// ---------------- helpers ------------------------------------------------------
__device__ __forceinline__ float block_reduce(float v, float* red) {
#pragma unroll
    for (int o = 16; o; o >>= 1) v += __shfl_down_sync(0xffffffffu, v, o);
    int t = threadIdx.x;
    if ((t & 31) == 0) red[t >> 5] = v;
    __syncthreads();
    float s = 0.f;
    if (t == 0) {
#pragma unroll
        for (int i = 0; i < TPB / 32; i++) s += red[i];
    }
    return s;          // valid on t==0 only
}

// ---------------- K1: full softmax + gate statistics (independent halves) -----
__global__ void __launch_bounds__(TPB) k1_soft_stats(
    const float* __restrict__ Z_i, const float* __restrict__ Z_j,
    const float* __restrict__ Gate,
    const int* __restrict__ si, const int* __restrict__ sj)
{
    const int bid = blockIdx.x;
    const int tid = threadIdx.x;

    if (bid < SOFT_BLOCKS) {
        // ---- full column softmax of Z_i / Z_j (consumed by K2) ----
        int c = bid * TPB + tid;
        if (c >= N_I + N_J) return;
        const float* src; float* dst; int n, cc;
        if (c < N_I) { src = Z_i; dst = g_SZi; n = N_I; cc = c; }
        else         { src = Z_j; dst = g_SZj; n = N_J; cc = c - N_I; }
        float v[KDIM];
        float mx = -1e30f;
#pragma unroll
        for (int a = 0; a < KDIM; a++) { v[a] = src[a * n + cc]; mx = fmaxf(mx, v[a]); }
        float sum = 0.f;
#pragma unroll
        for (int a = 0; a < KDIM; a++) { v[a] = __expf(v[a] - mx); sum += v[a]; }
        float inv = 1.f / sum;
#pragma unroll
        for (int a = 0; a < KDIM; a++) dst[a * n + cc] = v[a] * inv;
    } else {
        // ---- gate statistics s[b], T[a][b]; softmax recomputed inline ----
        int sb = bid - SOFT_BLOCKS;
        int gwarp = (sb * TPB + tid) >> 5;
        int lane = tid & 31;
        int nwarps = (STATS_BLOCKS * TPB) >> 5;

        float sacc = 0.f;
        float tacc[KDIM];
#pragma unroll
        for (int a = 0; a < KDIM; a++) tacc[a] = 0.f;

        for (int m = gwarp; m < M_I + M_J; m += nwarps) {
            int idx; const float* Zsrc; int n;
            if (m < M_I) { idx = si[m]; Zsrc = Z_i; n = N_I; }
            else         { idx = sj[m - M_I]; Zsrc = Z_j; n = N_J; }
            // inline softmax over the k axis for this column
            float zv = Zsrc[lane * n + idx];
            float mx = zv;
#pragma unroll
            for (int o = 16; o; o >>= 1) mx = fmaxf(mx, __shfl_xor_sync(0xffffffffu, mx, o));
            float e = __expf(zv - mx);
            float es = e;
#pragma unroll
            for (int o = 16; o; o >>= 1) es += __shfl_xor_sync(0xffffffffu, es, o);
            float z = e / es;

            float gt = Gate[idx * KDIM + lane];  // faithful: j-side indexes Gate w/o offset
            float g = 1.f / (1.f + __expf(-gt));
            float w = z * g;
            sacc += w;
#pragma unroll
            for (int a = 0; a < KDIM; a++) {
                float za = __shfl_sync(0xffffffffu, z, a);
                tacc[a] = fmaf(za, w, tacc[a]);
            }
        }
        atomicAdd(&g_s[lane], sacc);
#pragma unroll
        for (int a = 0; a < KDIM; a++) atomicAdd(&g_T[a * KDIM + lane], tacc[a]);
    }
}

// ---------------- K2: AZC (redundant per block) + per-node latent rows --------
__global__ void __launch_bounds__(TPB) k2_latent(const float* __restrict__ A) {
    __shared__ float az[DDIM][KDIM];
    const int tid = threadIdx.x;

    for (int e = tid; e < DDIM * KDIM; e += TPB) {
        int dd = e >> 5, b = e & 31;
        float acc = 0.f;
#pragma unroll
        for (int a = 0; a < KDIM; a++) acc = fmaf(A[dd * KDIM + a], g_T[a * KDIM + b], acc);
        az[dd][b] = acc / g_s[b];
    }
    __syncthreads();

    int c = blockIdx.x * TPB + tid;
    if (c >= N_I + N_J) return;
    const float* SZ; float* X; float* q; int n, cc, side;
    if (c < N_I) { SZ = g_SZi; X = g_Xi; q = g_qi; n = N_I; cc = c; side = 0; }
    else         { SZ = g_SZj; X = g_Xj; q = g_qj; n = N_J; cc = c - N_I; side = 1; }

    float x[DDIM];
#pragma unroll
    for (int dd = 0; dd < DDIM; dd++) x[dd] = 0.f;
#pragma unroll
    for (int a = 0; a < KDIM; a++) {
        float z = SZ[a * n + cc];
#pragma unroll
        for (int dd = 0; dd < DDIM; dd++) x[dd] = fmaf(az[dd][a], z, x[dd]);
    }
    float s2 = 0.f, s1 = 0.f;
    float4* o4 = (float4*)&X[cc * DDIM];
#pragma unroll
    for (int w = 0; w < DDIM / 4; w++) {
        float4 v4 = make_float4(x[4 * w], x[4 * w + 1], x[4 * w + 2], x[4 * w + 3]);
        s2 = fmaf(v4.x, v4.x, fmaf(v4.y, v4.y, fmaf(v4.z, v4.z, fmaf(v4.w, v4.w, s2))));
        s1 += v4.x + v4.y + v4.z + v4.w;
        o4[w] = v4;
    }
    q[cc] = side == 0 ? (s2 + 2.f * EPSV * s1) : (s2 - 2.f * EPSV * s1);
}

// ---------------- K3: pair tiles + edge chunks + final + cleanup --------------
__global__ void __launch_bounds__(TPB, 2) k3_pair_edges(
    const float* __restrict__ beta, const float* __restrict__ gamma,
    const int* __restrict__ si, const int* __restrict__ sj,
    const int* __restrict__ spi, const int* __restrict__ spj,
    float* __restrict__ out)
{
    __shared__ float s_As[KDIM][BT + 4];   // 528B row base stays 16B aligned
    __shared__ float s_Bs[KDIM][BT + 4];
    __shared__ float s_qa[BT], s_ba[BT], s_qb[BT], s_gb[BT];
    __shared__ float s_red[TPB / 32];

    const int tid = threadIdx.x;
    const int item = blockIdx.x;

    if (item < NPAIR) {
        // ---- dense pairwise exp-distance tile (BT x BT) ----
        int ti = item / NTJ, tj = item - ti * NTJ;
        int i0 = ti * BT, j0 = tj * BT;

        for (int e = tid; e < BT * KDIM; e += TPB) {
            int r = e >> 5, kk = e & 31;           // lanes sweep kk -> coalesced row reads
            int rg = i0 + r;
            float v = 0.f;
            if (rg < M_I) v = g_Xi[si[rg] * DDIM + kk];
            s_As[kk][r] = v;
            rg = j0 + r;
            v = 0.f;
            if (rg < M_J) v = g_Xj[sj[rg] * DDIM + kk];
            s_Bs[kk][r] = v;
        }
        if (tid < BT) {
            int rg = i0 + tid;
            if (rg < M_I) { int idx = si[rg]; s_qa[tid] = g_qi[idx]; s_ba[tid] = beta[idx]; }
            else          { s_qa[tid] = 1e30f; s_ba[tid] = 0.f; }
        } else {
            int p = tid - BT;
            int rg = j0 + p;
            if (rg < M_J) { int idx = sj[rg]; s_qb[p] = g_qj[idx]; s_gb[p] = gamma[idx]; }
            else          { s_qb[p] = 1e30f; s_gb[p] = 0.f; }
        }
        __syncthreads();

        const int tx = tid & 15, ty = tid >> 4;
        const int r0 = ty * 8, c0 = tx * 8;

        unsigned long long acc[8][4];
#pragma unroll
        for (int r = 0; r < 8; r++)
#pragma unroll
            for (int c = 0; c < 4; c++) acc[r][c] = 0ULL;

#pragma unroll
        for (int kk = 0; kk < KDIM; kk++) {
            float4 a0 = *(const float4*)&s_As[kk][r0];
            float4 a1 = *(const float4*)&s_As[kk][r0 + 4];
            ulonglong2 b0 = *(const ulonglong2*)&s_Bs[kk][c0];
            ulonglong2 b1 = *(const ulonglong2*)&s_Bs[kk][c0 + 4];
            float av[8] = {a0.x, a0.y, a0.z, a0.w, a1.x, a1.y, a1.z, a1.w};
            unsigned long long bp[4] = {b0.x, b0.y, b1.x, b1.y};
#pragma unroll
            for (int r = 0; r < 8; r++) {
                unsigned long long ad;
                asm("mov.b64 %0, {%1, %1};" : "=l"(ad) : "f"(av[r]));
#pragma unroll
                for (int c = 0; c < 4; c++) {
                    asm("fma.rn.f32x2 %0, %1, %2, %0;" : "+l"(acc[r][c]) : "l"(ad), "l"(bp[c]));
                }
            }
        }

        float sum = 0.f;
#pragma unroll
        for (int r = 0; r < 8; r++) {
            float qa = s_qa[r0 + r];
            float ba = s_ba[r0 + r];
#pragma unroll
            for (int c = 0; c < 4; c++) {
                float dlo, dhi;
                asm("mov.b64 {%0, %1}, %2;" : "=f"(dlo), "=f"(dhi) : "l"(acc[r][c]));
                int cl = c0 + 2 * c;
                float d2a = qa + s_qb[cl] - 2.f * dlo + C0;
                float d2b = qa + s_qb[cl + 1] - 2.f * dhi + C0;
                d2a = fmaxf(d2a, 0.f);
                d2b = fmaxf(d2b, 0.f);
                sum += __expf(ba + s_gb[cl] - sqrtf(d2a));
                sum += __expf(ba + s_gb[cl + 1] - sqrtf(d2b));
            }
        }
        float bs = block_reduce(sum, s_red);
        if (tid == 0) atomicAdd(&g_mat, (double)bs);
    } else {
        // ---- sparse edge chunk ----
        int base = (item - NPAIR) * EDGE_PER_BLK;
        float sum = 0.f;
#pragma unroll
        for (int l = 0; l < EDGE_PER_BLK / TPB; l++) {
            int e = base + l * TPB + tid;
            if (e < N_EDGES) {
                int ii = spi[e];
                int jj = spj[e];
                const float4* xa = (const float4*)&g_Xi[ii * DDIM];
                const float4* xb = (const float4*)&g_Xj[jj * DDIM];
                float dot = 0.f;
#pragma unroll
                for (int w = 0; w < DDIM / 4; w++) {
                    float4 a = xa[w], b = xb[w];
                    dot = fmaf(a.x, b.x, dot);
                    dot = fmaf(a.y, b.y, dot);
                    dot = fmaf(a.z, b.z, dot);
                    dot = fmaf(a.w, b.w, dot);
                }
                float d2 = g_qi[ii] + g_qj[jj] - 2.f * dot + C0;
                d2 = fmaxf(d2, 0.f);
                sum += beta[ii] + gamma[jj] - sqrtf(d2);
            }
        }
        float bs = block_reduce(sum, s_red);
        if (tid == 0) atomicAdd(&g_links, (double)bs);
    }

    // ---- last-block-done: final scalar + reset accumulators for next replay ----
    __syncthreads();
    __threadfence();
    __shared__ unsigned int s_last;
    if (tid == 0) s_last = atomicAdd(&g_done, 1u);
    __syncthreads();
    if (s_last == K3_BLOCKS - 1) {
        if (tid == 0) {
            double m = atomicAdd(&g_mat, 0.0);      // acquire-ish read after fence chain
            double l = atomicAdd(&g_links, 0.0);
            out[0] = (float)(l - m);
            g_mat = 0.0;
            g_links = 0.0;
            g_done = 0u;
            g_s[0] = 0.f;
        }
        // re-zero stats accumulators so next replay starts clean
        for (int e = tid; e < KDIM * KDIM; e += TPB) g_T[e] = 0.f;
        if (tid > 0 && tid < KDIM) g_s[tid] = 0.f;
    }
}

// ---------------- launcher -----------------------------------------------------
extern "C" void kernel_launch(void* const* d_in, const int* in_sizes, int n_in,
                              void* d_out, int out_size) {
    const float* beta  = (const float*)d_in[0];
    const float* gamma = (const float*)d_in[1];
    const float* A     = (const float*)d_in[2];
    const float* Z_i   = (const float*)d_in[3];
    const float* Z_j   = (const float*)d_in[4];
    const float* Gate  = (const float*)d_in[5];
    const int* si      = (const int*)d_in[6];
    const int* sj      = (const int*)d_in[7];
    const int* spi     = (const int*)d_in[8];
    const int* spj     = (const int*)d_in[9];
    float* out = (float*)d_out;

    k1_soft_stats<<<K1_BLOCKS, TPB>>>(Z_i, Z_j, Gate, si, sj);
    k2_latent<<<(N_I + N_J + TPB - 1) / TPB, TPB>>>(A);
    k3_pair_edges<<<K3_BLOCKS, TPB>>>(beta, gamma, si, sj, spi, spj, out);
}

// round 8
// speedup vs baseline: 1.1991x; 1.1945x over previous
#include <cuda_runtime.h>
#include <cuda_bf16.h>
#include <math.h>

// Problem shapes (fixed for this dataset)
#define KDIM 32
#define DDIM 32
#define N_I 5000
#define N_J 5000
#define M_I 2500
#define M_J 2500
#define N_EDGES 200000
#define EPSV 1e-6f
#define C0 (32.0f * EPSV * EPSV)

#define TPB 256
#define BT 128                        // pair tile edge
#define NTI ((M_I + BT - 1) / BT)     // 20
#define NTJ ((M_J + BT - 1) / BT)     // 20
#define NPAIR (NTI * NTJ)             // 400
#define EDGE_PER_BLK 2048
#define NEDGE_BLKS ((N_EDGES + EDGE_PER_BLK - 1) / EDGE_PER_BLK)  // 98
#define K3_BLOCKS (NPAIR + NEDGE_BLKS)                            // 498

#define SOFT_BLOCKS ((N_I + N_J + TPB - 1) / TPB)   // 40
#define STATS_BLOCKS 100                            // 5x more stats warps (was 20)
#define K1_BLOCKS (SOFT_BLOCKS + STATS_BLOCKS)      // 140 ~= one full wave

// ---------------- scratch (static device globals; zero-initialized) ----------
// INVARIANT: g_T, g_s, g_mat, g_links, g_done are zero at kernel_launch entry.
// They start zero (module load) and K3's final block re-zeroes them each call.
__device__ float g_SZi[KDIM * N_I];      // softmax(Z_i) (k, n_i)
__device__ float g_SZj[KDIM * N_J];      // softmax(Z_j) (k, n_j)
__device__ float g_T[KDIM * KDIM];       // T[a][b] = sum_m Z[a,m] Z[b,m] G[m,b]
__device__ float g_s[KDIM];              // s[b]
__device__ float g_Xi[N_I * DDIM];       // latent rows (128B each)
__device__ float g_qi[N_I];              // ||x||^2 + 2 eps sum(x)
__device__ float g_Xj[N_J * DDIM];
__device__ float g_qj[N_J];              // ||x||^2 - 2 eps sum(x)
__device__ double g_mat;
__device__ double g_links;
__device__ unsigned int g_done;

// ---------------- helpers ------------------------------------------------------
__device__ __forceinline__ float block_reduce(float v, float* red) {
#pragma unroll
    for (int o = 16; o; o >>= 1) v += __shfl_down_sync(0xffffffffu, v, o);
    int t = threadIdx.x;
    if ((t & 31) == 0) red[t >> 5] = v;
    __syncthreads();
    float s = 0.f;
    if (t == 0) {
#pragma unroll
        for (int i = 0; i < TPB / 32; i++) s += red[i];
    }
    return s;          // valid on t==0 only
}

// ---------------- K1: full softmax + gate statistics (independent halves) -----
__global__ void __launch_bounds__(TPB) k1_soft_stats(
    const float* __restrict__ Z_i, const float* __restrict__ Z_j,
    const float* __restrict__ Gate,
    const int* __restrict__ si, const int* __restrict__ sj)
{
    const int bid = blockIdx.x;
    const int tid = threadIdx.x;

    if (bid < SOFT_BLOCKS) {
        // ---- full column softmax of Z_i / Z_j (consumed by K2) ----
        int c = bid * TPB + tid;
        if (c >= N_I + N_J) return;
        const float* src; float* dst; int n, cc;
        if (c < N_I) { src = Z_i; dst = g_SZi; n = N_I; cc = c; }
        else         { src = Z_j; dst = g_SZj; n = N_J; cc = c - N_I; }
        float v[KDIM];
        float mx = -1e30f;
#pragma unroll
        for (int a = 0; a < KDIM; a++) { v[a] = src[a * n + cc]; mx = fmaxf(mx, v[a]); }
        float sum = 0.f;
#pragma unroll
        for (int a = 0; a < KDIM; a++) { v[a] = __expf(v[a] - mx); sum += v[a]; }
        float inv = 1.f / sum;
#pragma unroll
        for (int a = 0; a < KDIM; a++) dst[a * n + cc] = v[a] * inv;
    } else {
        // ---- gate statistics s[b], T[a][b]; softmax recomputed inline ----
        int sb = bid - SOFT_BLOCKS;
        int gwarp = (sb * TPB + tid) >> 5;
        int lane = tid & 31;
        int nwarps = (STATS_BLOCKS * TPB) >> 5;   // 800 warps -> ~6 samples each

        float sacc = 0.f;
        float tacc[KDIM];
#pragma unroll
        for (int a = 0; a < KDIM; a++) tacc[a] = 0.f;

        for (int m = gwarp; m < M_I + M_J; m += nwarps) {
            int idx; const float* Zsrc; int n;
            if (m < M_I) { idx = si[m]; Zsrc = Z_i; n = N_I; }
            else         { idx = sj[m - M_I]; Zsrc = Z_j; n = N_J; }
            // inline softmax over the k axis for this column
            float zv = Zsrc[lane * n + idx];
            float mx = zv;
#pragma unroll
            for (int o = 16; o; o >>= 1) mx = fmaxf(mx, __shfl_xor_sync(0xffffffffu, mx, o));
            float e = __expf(zv - mx);
            float es = e;
#pragma unroll
            for (int o = 16; o; o >>= 1) es += __shfl_xor_sync(0xffffffffu, es, o);
            float z = e / es;

            float gt = Gate[idx * KDIM + lane];  // faithful: j-side indexes Gate w/o offset
            float g = 1.f / (1.f + __expf(-gt));
            float w = z * g;
            sacc += w;
#pragma unroll
            for (int a = 0; a < KDIM; a++) {
                float za = __shfl_sync(0xffffffffu, z, a);
                tacc[a] = fmaf(za, w, tacc[a]);
            }
        }
        atomicAdd(&g_s[lane], sacc);
#pragma unroll
        for (int a = 0; a < KDIM; a++) atomicAdd(&g_T[a * KDIM + lane], tacc[a]);
    }
}

// ---------------- K2: AZC (redundant per block) + per-node latent rows --------
__global__ void __launch_bounds__(TPB) k2_latent(const float* __restrict__ A) {
    __shared__ float az[DDIM][KDIM];
    const int tid = threadIdx.x;

    for (int e = tid; e < DDIM * KDIM; e += TPB) {
        int dd = e >> 5, b = e & 31;
        float acc = 0.f;
#pragma unroll
        for (int a = 0; a < KDIM; a++) acc = fmaf(A[dd * KDIM + a], g_T[a * KDIM + b], acc);
        az[dd][b] = acc / g_s[b];
    }
    __syncthreads();

    int c = blockIdx.x * TPB + tid;
    if (c >= N_I + N_J) return;
    const float* SZ; float* X; float* q; int n, cc, side;
    if (c < N_I) { SZ = g_SZi; X = g_Xi; q = g_qi; n = N_I; cc = c; side = 0; }
    else         { SZ = g_SZj; X = g_Xj; q = g_qj; n = N_J; cc = c - N_I; side = 1; }

    float x[DDIM];
#pragma unroll
    for (int dd = 0; dd < DDIM; dd++) x[dd] = 0.f;
#pragma unroll
    for (int a = 0; a < KDIM; a++) {
        float z = SZ[a * n + cc];
#pragma unroll
        for (int dd = 0; dd < DDIM; dd++) x[dd] = fmaf(az[dd][a], z, x[dd]);
    }
    float s2 = 0.f, s1 = 0.f;
    float4* o4 = (float4*)&X[cc * DDIM];
#pragma unroll
    for (int w = 0; w < DDIM / 4; w++) {
        float4 v4 = make_float4(x[4 * w], x[4 * w + 1], x[4 * w + 2], x[4 * w + 3]);
        s2 = fmaf(v4.x, v4.x, fmaf(v4.y, v4.y, fmaf(v4.z, v4.z, fmaf(v4.w, v4.w, s2))));
        s1 += v4.x + v4.y + v4.z + v4.w;
        o4[w] = v4;
    }
    q[cc] = side == 0 ? (s2 + 2.f * EPSV * s1) : (s2 - 2.f * EPSV * s1);
}

// ---------------- K3: pair tiles + edge chunks + final + cleanup --------------
__global__ void __launch_bounds__(TPB, 2) k3_pair_edges(
    const float* __restrict__ beta, const float* __restrict__ gamma,
    const int* __restrict__ si, const int* __restrict__ sj,
    const int* __restrict__ spi, const int* __restrict__ spj,
    float* __restrict__ out)
{
    __shared__ float s_As[KDIM][BT + 4];   // 528B row base stays 16B aligned
    __shared__ float s_Bs[KDIM][BT + 4];
    __shared__ float s_qa[BT], s_ba[BT], s_qb[BT], s_gb[BT];
    __shared__ float s_red[TPB / 32];

    const int tid = threadIdx.x;
    const int item = blockIdx.x;

    if (item < NPAIR) {
        // ---- dense pairwise exp-distance tile (BT x BT) ----
        int ti = item / NTJ, tj = item - ti * NTJ;
        int i0 = ti * BT, j0 = tj * BT;

        for (int e = tid; e < BT * KDIM; e += TPB) {
            int r = e >> 5, kk = e & 31;           // lanes sweep kk -> coalesced row reads
            int rg = i0 + r;
            float v = 0.f;
            if (rg < M_I) v = g_Xi[si[rg] * DDIM + kk];
            s_As[kk][r] = v;
            rg = j0 + r;
            v = 0.f;
            if (rg < M_J) v = g_Xj[sj[rg] * DDIM + kk];
            s_Bs[kk][r] = v;
        }
        if (tid < BT) {
            int rg = i0 + tid;
            if (rg < M_I) { int idx = si[rg]; s_qa[tid] = g_qi[idx]; s_ba[tid] = beta[idx]; }
            else          { s_qa[tid] = 1e30f; s_ba[tid] = 0.f; }
        } else {
            int p = tid - BT;
            int rg = j0 + p;
            if (rg < M_J) { int idx = sj[rg]; s_qb[p] = g_qj[idx]; s_gb[p] = gamma[idx]; }
            else          { s_qb[p] = 1e30f; s_gb[p] = 0.f; }
        }
        __syncthreads();

        const int tx = tid & 15, ty = tid >> 4;
        const int r0 = ty * 8, c0 = tx * 8;

        unsigned long long acc[8][4];
#pragma unroll
        for (int r = 0; r < 8; r++)
#pragma unroll
            for (int c = 0; c < 4; c++) acc[r][c] = 0ULL;

#pragma unroll
        for (int kk = 0; kk < KDIM; kk++) {
            float4 a0 = *(const float4*)&s_As[kk][r0];
            float4 a1 = *(const float4*)&s_As[kk][r0 + 4];
            ulonglong2 b0 = *(const ulonglong2*)&s_Bs[kk][c0];
            ulonglong2 b1 = *(const ulonglong2*)&s_Bs[kk][c0 + 4];
            float av[8] = {a0.x, a0.y, a0.z, a0.w, a1.x, a1.y, a1.z, a1.w};
            unsigned long long bp[4] = {b0.x, b0.y, b1.x, b1.y};
#pragma unroll
            for (int r = 0; r < 8; r++) {
                unsigned long long ad;
                asm("mov.b64 %0, {%1, %1};" : "=l"(ad) : "f"(av[r]));
#pragma unroll
                for (int c = 0; c < 4; c++) {
                    asm("fma.rn.f32x2 %0, %1, %2, %0;" : "+l"(acc[r][c]) : "l"(ad), "l"(bp[c]));
                }
            }
        }

        float sum = 0.f;
#pragma unroll
        for (int r = 0; r < 8; r++) {
            float qa = s_qa[r0 + r];
            float ba = s_ba[r0 + r];
#pragma unroll
            for (int c = 0; c < 4; c++) {
                float dlo, dhi;
                asm("mov.b64 {%0, %1}, %2;" : "=f"(dlo), "=f"(dhi) : "l"(acc[r][c]));
                int cl = c0 + 2 * c;
                float d2a = qa + s_qb[cl] - 2.f * dlo + C0;
                float d2b = qa + s_qb[cl + 1] - 2.f * dhi + C0;
                d2a = fmaxf(d2a, 0.f);
                d2b = fmaxf(d2b, 0.f);
                sum += __expf(ba + s_gb[cl] - sqrtf(d2a));
                sum += __expf(ba + s_gb[cl + 1] - sqrtf(d2b));
            }
        }
        float bs = block_reduce(sum, s_red);
        if (tid == 0) atomicAdd(&g_mat, (double)bs);
    } else {
        // ---- sparse edge chunk ----
        int base = (item - NPAIR) * EDGE_PER_BLK;
        float sum = 0.f;
#pragma unroll
        for (int l = 0; l < EDGE_PER_BLK / TPB; l++) {
            int e = base + l * TPB + tid;
            if (e < N_EDGES) {
                int ii = spi[e];
                int jj = spj[e];
                const float4* xa = (const float4*)&g_Xi[ii * DDIM];
                const float4* xb = (const float4*)&g_Xj[jj * DDIM];
                float dot = 0.f;
#pragma unroll
                for (int w = 0; w < DDIM / 4; w++) {
                    float4 a = xa[w], b = xb[w];
                    dot = fmaf(a.x, b.x, dot);
                    dot = fmaf(a.y, b.y, dot);
                    dot = fmaf(a.z, b.z, dot);
                    dot = fmaf(a.w, b.w, dot);
                }
                float d2 = g_qi[ii] + g_qj[jj] - 2.f * dot + C0;
                d2 = fmaxf(d2, 0.f);
                sum += beta[ii] + gamma[jj] - sqrtf(d2);
            }
        }
        float bs = block_reduce(sum, s_red);
        if (tid == 0) atomicAdd(&g_links, (double)bs);
    }

    // ---- last-block-done: final scalar + reset accumulators for next replay ----
    __syncthreads();
    __threadfence();
    __shared__ unsigned int s_last;
    if (tid == 0) s_last = atomicAdd(&g_done, 1u);
    __syncthreads();
    if (s_last == K3_BLOCKS - 1) {
        if (tid == 0) {
            double m = atomicAdd(&g_mat, 0.0);      // read after fence chain
            double l = atomicAdd(&g_links, 0.0);
            out[0] = (float)(l - m);
            g_mat = 0.0;
            g_links = 0.0;
            g_done = 0u;
            g_s[0] = 0.f;
        }
        // re-zero stats accumulators so next replay starts clean
        for (int e = tid; e < KDIM * KDIM; e += TPB) g_T[e] = 0.f;
        if (tid > 0 && tid < KDIM) g_s[tid] = 0.f;
    }
}

// ---------------- launcher -----------------------------------------------------
extern "C" void kernel_launch(void* const* d_in, const int* in_sizes, int n_in,
                              void* d_out, int out_size) {
    const float* beta  = (const float*)d_in[0];
    const float* gamma = (const float*)d_in[1];
    const float* A     = (const float*)d_in[2];
    const float* Z_i   = (const float*)d_in[3];
    const float* Z_j   = (const float*)d_in[4];
    const float* Gate  = (const float*)d_in[5];
    const int* si      = (const int*)d_in[6];
    const int* sj      = (const int*)d_in[7];
    const int* spi     = (const int*)d_in[8];
    const int* spj     = (const int*)d_in[9];
    float* out = (float*)d_out;

    k1_soft_stats<<<K1_BLOCKS, TPB>>>(Z_i, Z_j, Gate, si, sj);
    k2_latent<<<(N_I + N_J + TPB - 1) / TPB, TPB>>>(A);
    k3_pair_edges<<<K3_BLOCKS, TPB>>>(beta, gamma, si, sj, spi, spj, out);
}

// round 12
// speedup vs baseline: 1.4504x; 1.2096x over previous
#include <cuda_runtime.h>
#include <cuda_bf16.h>
#include <math.h>

// Problem shapes (fixed for this dataset)
#define KDIM 32
#define DDIM 32
#define N_I 5000
#define N_J 5000
#define M_I 2500
#define M_J 2500
#define N_EDGES 200000
#define EPSV 1e-6f
#define C0 (32.0f * EPSV * EPSV)

#define BT 128                        // pair tile edge
#define NTI ((M_I + BT - 1) / BT)     // 20
#define NTJ ((M_J + BT - 1) / BT)     // 20
#define NPAIR (NTI * NTJ)             // 400
#define EDGE_PER_BLK 2048
#define NEDGE_BLKS ((N_EDGES + EDGE_PER_BLK - 1) / EDGE_PER_BLK)  // 98
#define NITEMS (NPAIR + NEDGE_BLKS)                               // 498

#define K1_TPB 256
#define K1_BLOCKS 216                 // 1728 warps, warp-per-sample stats
#define K2_TPB 128
#define K2_BLOCKS ((N_I + N_J + K2_TPB - 1) / K2_TPB)   // 79
#define K3_TPB 256
#define K3_GRID 296                   // 2 blocks/SM on 148 SMs; item loop, no tail wave

// ---------------- scratch (static device globals; zero-initialized) ----------
// INVARIANT: g_T, g_s, g_mat, g_links, g_done are zero at kernel_launch entry.
// They start zero (module load) and K3's final block re-zeroes them each call.
__device__ float g_T[KDIM * KDIM];       // T[a][b] = sum_m Z[a,m] Z[b,m] G[m,b]
__device__ float g_s[KDIM];              // s[b]
__device__ float g_Xi[N_I * DDIM];       // latent rows (128B each)
__device__ float g_qi[N_I];              // ||x||^2 + 2 eps sum(x)
__device__ float g_Xj[N_J * DDIM];
__device__ float g_qj[N_J];              // ||x||^2 - 2 eps sum(x)
__device__ double g_mat;
__device__ double g_links;
__device__ unsigned int g_done;

// ---------------- helpers ------------------------------------------------------
__device__ __forceinline__ float block_reduce(float v, float* red) {
#pragma unroll
    for (int o = 16; o; o >>= 1) v += __shfl_down_sync(0xffffffffu, v, o);
    int t = threadIdx.x;
    if ((t & 31) == 0) red[t >> 5] = v;
    __syncthreads();
    float s = 0.f;
    if (t == 0) {
#pragma unroll
        for (int i = 0; i < K3_TPB / 32; i++) s += red[i];
    }
    return s;          // valid on t==0 only
}

// ---------------- K1: gate statistics only (softmax recomputed inline) --------
__global__ void __launch_bounds__(K1_TPB) k1_stats(
    const float* __restrict__ Z_i, const float* __restrict__ Z_j,
    const float* __restrict__ Gate,
    const int* __restrict__ si, const int* __restrict__ sj)
{
    const int tid = threadIdx.x;
    const int lane = tid & 31;
    const int gwarp = (blockIdx.x * K1_TPB + tid) >> 5;
    const int nwarps = (K1_BLOCKS * K1_TPB) >> 5;   // 1728 warps -> ~2.9 samples each

    float sacc = 0.f;
    float tacc[KDIM];
#pragma unroll
    for (int a = 0; a < KDIM; a++) tacc[a] = 0.f;

    for (int m = gwarp; m < M_I + M_J; m += nwarps) {
        int idx; const float* Zsrc; int n;
        if (m < M_I) { idx = si[m]; Zsrc = Z_i; n = N_I; }
        else         { idx = sj[m - M_I]; Zsrc = Z_j; n = N_J; }
        float gt = Gate[idx * KDIM + lane];  // issue early (independent of reductions)
        // inline softmax over the k axis for this column
        float zv = Zsrc[lane * n + idx];
        float mx = zv;
#pragma unroll
        for (int o = 16; o; o >>= 1) mx = fmaxf(mx, __shfl_xor_sync(0xffffffffu, mx, o));
        float e = __expf(zv - mx);
        float es = e;
#pragma unroll
        for (int o = 16; o; o >>= 1) es += __shfl_xor_sync(0xffffffffu, es, o);
        float z = e / es;

        float g = 1.f / (1.f + __expf(-gt));   // faithful: j-side indexes Gate w/o offset
        float w = z * g;
        sacc += w;
#pragma unroll
        for (int a = 0; a < KDIM; a++) {
            float za = __shfl_sync(0xffffffffu, z, a);
            tacc[a] = fmaf(za, w, tacc[a]);
        }
    }
    atomicAdd(&g_s[lane], sacc);
#pragma unroll
    for (int a = 0; a < KDIM; a++) atomicAdd(&g_T[a * KDIM + lane], tacc[a]);
}

// ---------------- K2: AZC (redundant per block) + latent rows (inline softmax) -
__global__ void __launch_bounds__(K2_TPB) k2_latent(
    const float* __restrict__ A,
    const float* __restrict__ Z_i, const float* __restrict__ Z_j)
{
    __shared__ float az[DDIM][KDIM];
    const int tid = threadIdx.x;

    for (int e = tid; e < DDIM * KDIM; e += K2_TPB) {
        int dd = e >> 5, b = e & 31;
        float acc = 0.f;
#pragma unroll
        for (int a = 0; a < KDIM; a++) acc = fmaf(A[dd * KDIM + a], g_T[a * KDIM + b], acc);
        az[dd][b] = acc / g_s[b];
    }
    __syncthreads();

    int c = blockIdx.x * K2_TPB + tid;
    if (c >= N_I + N_J) return;
    const float* Zsrc; float* X; float* q; int n, cc, side;
    if (c < N_I) { Zsrc = Z_i; X = g_Xi; q = g_qi; n = N_I; cc = c; side = 0; }
    else         { Zsrc = Z_j; X = g_Xj; q = g_qj; n = N_J; cc = c - N_I; side = 1; }

    // inline column softmax (register-local)
    float v[KDIM];
    float mx = -1e30f;
#pragma unroll
    for (int a = 0; a < KDIM; a++) { v[a] = Zsrc[a * n + cc]; mx = fmaxf(mx, v[a]); }
    float sum = 0.f;
#pragma unroll
    for (int a = 0; a < KDIM; a++) { v[a] = __expf(v[a] - mx); sum += v[a]; }
    float inv = 1.f / sum;

    float x[DDIM];
#pragma unroll
    for (int dd = 0; dd < DDIM; dd++) x[dd] = 0.f;
#pragma unroll
    for (int a = 0; a < KDIM; a++) {
        float z = v[a] * inv;
#pragma unroll
        for (int dd = 0; dd < DDIM; dd++) x[dd] = fmaf(az[dd][a], z, x[dd]);
    }
    float s2 = 0.f, s1 = 0.f;
    float4* o4 = (float4*)&X[cc * DDIM];
#pragma unroll
    for (int w = 0; w < DDIM / 4; w++) {
        float4 v4 = make_float4(x[4 * w], x[4 * w + 1], x[4 * w + 2], x[4 * w + 3]);
        s2 = fmaf(v4.x, v4.x, fmaf(v4.y, v4.y, fmaf(v4.z, v4.z, fmaf(v4.w, v4.w, s2))));
        s1 += v4.x + v4.y + v4.z + v4.w;
        o4[w] = v4;
    }
    q[cc] = side == 0 ? (s2 + 2.f * EPSV * s1) : (s2 - 2.f * EPSV * s1);
}

// ---------------- K3: pair tiles + edge chunks (item loop) --------------------
__global__ void __launch_bounds__(K3_TPB, 2) k3_pair_edges(
    const float* __restrict__ beta, const float* __restrict__ gamma,
    const int* __restrict__ si, const int* __restrict__ sj,
    const int* __restrict__ spi, const int* __restrict__ spj,
    float* __restrict__ out)
{
    __shared__ float s_As[KDIM][BT + 4];   // 528B row base stays 16B aligned
    __shared__ float s_Bs[KDIM][BT + 4];
    __shared__ float s_qa[BT], s_ba[BT], s_qb[BT], s_gb[BT];
    __shared__ float s_red[K3_TPB / 32];

    const int tid = threadIdx.x;

    for (int item = blockIdx.x; item < NITEMS; item += K3_GRID) {
        __syncthreads();   // protect smem reuse across item iterations
        if (item < NPAIR) {
            // ---- dense pairwise exp-distance tile (BT x BT) ----
            int ti = item / NTJ, tj = item - ti * NTJ;
            int i0 = ti * BT, j0 = tj * BT;

            for (int e = tid; e < BT * KDIM; e += K3_TPB) {
                int r = e >> 5, kk = e & 31;       // lanes sweep kk -> coalesced row reads
                int rg = i0 + r;
                float v = 0.f;
                if (rg < M_I) v = g_Xi[si[rg] * DDIM + kk];
                s_As[kk][r] = v;
                rg = j0 + r;
                v = 0.f;
                if (rg < M_J) v = g_Xj[sj[rg] * DDIM + kk];
                s_Bs[kk][r] = v;
            }
            if (tid < BT) {
                int rg = i0 + tid;
                if (rg < M_I) { int idx = si[rg]; s_qa[tid] = g_qi[idx]; s_ba[tid] = beta[idx]; }
                else          { s_qa[tid] = 1e30f; s_ba[tid] = 0.f; }
            } else {
                int p = tid - BT;
                int rg = j0 + p;
                if (rg < M_J) { int idx = sj[rg]; s_qb[p] = g_qj[idx]; s_gb[p] = gamma[idx]; }
                else          { s_qb[p] = 1e30f; s_gb[p] = 0.f; }
            }
            __syncthreads();

            const int tx = tid & 15, ty = tid >> 4;
            const int r0 = ty * 8, c0 = tx * 8;

            unsigned long long acc[8][4];
#pragma unroll
            for (int r = 0; r < 8; r++)
#pragma unroll
                for (int c = 0; c < 4; c++) acc[r][c] = 0ULL;

#pragma unroll
            for (int kk = 0; kk < KDIM; kk++) {
                float4 a0 = *(const float4*)&s_As[kk][r0];
                float4 a1 = *(const float4*)&s_As[kk][r0 + 4];
                ulonglong2 b0 = *(const ulonglong2*)&s_Bs[kk][c0];
                ulonglong2 b1 = *(const ulonglong2*)&s_Bs[kk][c0 + 4];
                float av[8] = {a0.x, a0.y, a0.z, a0.w, a1.x, a1.y, a1.z, a1.w};
                unsigned long long bp[4] = {b0.x, b0.y, b1.x, b1.y};
#pragma unroll
                for (int r = 0; r < 8; r++) {
                    unsigned long long ad;
                    asm("mov.b64 %0, {%1, %1};" : "=l"(ad) : "f"(av[r]));
#pragma unroll
                    for (int c = 0; c < 4; c++) {
                        asm("fma.rn.f32x2 %0, %1, %2, %0;"
                            : "+l"(acc[r][c]) : "l"(ad), "l"(bp[c]));
                    }
                }
            }

            float sum = 0.f;
#pragma unroll
            for (int r = 0; r < 8; r++) {
                float qa = s_qa[r0 + r];
                float ba = s_ba[r0 + r];
#pragma unroll
                for (int c = 0; c < 4; c++) {
                    float dlo, dhi;
                    asm("mov.b64 {%0, %1}, %2;" : "=f"(dlo), "=f"(dhi) : "l"(acc[r][c]));
                    int cl = c0 + 2 * c;
                    float d2a = qa + s_qb[cl] - 2.f * dlo + C0;
                    float d2b = qa + s_qb[cl + 1] - 2.f * dhi + C0;
                    d2a = fmaxf(d2a, 0.f);
                    d2b = fmaxf(d2b, 0.f);
                    sum += __expf(ba + s_gb[cl] - sqrtf(d2a));
                    sum += __expf(ba + s_gb[cl + 1] - sqrtf(d2b));
                }
            }
            float bs = block_reduce(sum, s_red);
            if (tid == 0) atomicAdd(&g_mat, (double)bs);
        } else {
            // ---- sparse edge chunk ----
            int base = (item - NPAIR) * EDGE_PER_BLK;
            float sum = 0.f;
#pragma unroll
            for (int l = 0; l < EDGE_PER_BLK / K3_TPB; l++) {
                int e = base + l * K3_TPB + tid;
                if (e < N_EDGES) {
                    int ii = spi[e];
                    int jj = spj[e];
                    const float4* xa = (const float4*)&g_Xi[ii * DDIM];
                    const float4* xb = (const float4*)&g_Xj[jj * DDIM];
                    float dot = 0.f;
#pragma unroll
                    for (int w = 0; w < DDIM / 4; w++) {
                        float4 a = xa[w], b = xb[w];
                        dot = fmaf(a.x, b.x, dot);
                        dot = fmaf(a.y, b.y, dot);
                        dot = fmaf(a.z, b.z, dot);
                        dot = fmaf(a.w, b.w, dot);
                    }
                    float d2 = g_qi[ii] + g_qj[jj] - 2.f * dot + C0;
                    d2 = fmaxf(d2, 0.f);
                    sum += beta[ii] + gamma[jj] - sqrtf(d2);
                }
            }
            float bs = block_reduce(sum, s_red);
            if (tid == 0) atomicAdd(&g_links, (double)bs);
        }
    }

    // ---- last-block-done: final scalar + reset accumulators for next replay ----
    __syncthreads();
    __threadfence();
    __shared__ unsigned int s_last;
    if (tid == 0) s_last = atomicAdd(&g_done, 1u);
    __syncthreads();
    if (s_last == K3_GRID - 1) {
        if (tid == 0) {
            double m = atomicAdd(&g_mat, 0.0);      // read after fence chain
            double l = atomicAdd(&g_links, 0.0);
            out[0] = (float)(l - m);
            g_mat = 0.0;
            g_links = 0.0;
            g_done = 0u;
            g_s[0] = 0.f;
        }
        // re-zero stats accumulators so next replay starts clean
        for (int e = tid; e < KDIM * KDIM; e += K3_TPB) g_T[e] = 0.f;
        if (tid > 0 && tid < KDIM) g_s[tid] = 0.f;
    }
}

// ---------------- launcher -----------------------------------------------------
extern "C" void kernel_launch(void* const* d_in, const int* in_sizes, int n_in,
                              void* d_out, int out_size) {
    const float* beta  = (const float*)d_in[0];
    const float* gamma = (const float*)d_in[1];
    const float* A     = (const float*)d_in[2];
    const float* Z_i   = (const float*)d_in[3];
    const float* Z_j   = (const float*)d_in[4];
    const float* Gate  = (const float*)d_in[5];
    const int* si      = (const int*)d_in[6];
    const int* sj      = (const int*)d_in[7];
    const int* spi     = (const int*)d_in[8];
    const int* spj     = (const int*)d_in[9];
    float* out = (float*)d_out;

    k1_stats<<<K1_BLOCKS, K1_TPB>>>(Z_i, Z_j, Gate, si, sj);
    k2_latent<<<K2_BLOCKS, K2_TPB>>>(A, Z_i, Z_j);
    k3_pair_edges<<<K3_GRID, K3_TPB>>>(beta, gamma, si, sj, spi, spj, out);
}

// round 13
// speedup vs baseline: 1.7417x; 1.2009x over previous
#include <cuda_runtime.h>
#include <cuda_bf16.h>
#include <math.h>

// Problem shapes (fixed for this dataset)
#define KDIM 32
#define DDIM 32
#define N_I 5000
#define N_J 5000
#define M_I 2500
#define M_J 2500
#define N_EDGES 200000
#define EPSV 1e-6f
#define C0 (32.0f * EPSV * EPSV)

#define BT 128                        // pair tile edge
#define NTI ((M_I + BT - 1) / BT)     // 20
#define NTJ ((M_J + BT - 1) / BT)     // 20
#define NPAIR (NTI * NTJ)             // 400
#define EDGE_PER_BLK 2048
#define NEDGE_BLKS ((N_EDGES + EDGE_PER_BLK - 1) / EDGE_PER_BLK)  // 98
#define NITEMS (NPAIR + NEDGE_BLKS)                               // 498

#define K1_TPB 256
#define K1_BLOCKS 128                 // 1024 warps; smem-reduced stats (atomic tail /45)
#define K2_TPB 128
#define K2_BLOCKS ((N_I + N_J + K2_TPB - 1) / K2_TPB)   // 79
#define K3_TPB 256
#define K3_GRID 296                   // 2 blocks/SM on 148 SMs; item loop, no tail wave

// ---------------- scratch (static device globals; zero-initialized) ----------
// INVARIANT: g_T, g_s, g_mat, g_links, g_done are zero at kernel_launch entry.
// They start zero (module load) and K3's final block re-zeroes them each call.
__device__ float g_T[KDIM * KDIM];       // T[a][b] = sum_m Z[a,m] Z[b,m] G[m,b]
__device__ float g_s[KDIM];              // s[b]
__device__ float g_Xi[N_I * DDIM];       // latent rows (128B each)
__device__ float g_qi[N_I];              // ||x||^2 + 2 eps sum(x)
__device__ float g_Xj[N_J * DDIM];
__device__ float g_qj[N_J];              // ||x||^2 - 2 eps sum(x)
__device__ double g_mat;
__device__ double g_links;
__device__ unsigned int g_done;

// ---------------- helpers ------------------------------------------------------
__device__ __forceinline__ float block_reduce(float v, float* red) {
#pragma unroll
    for (int o = 16; o; o >>= 1) v += __shfl_down_sync(0xffffffffu, v, o);
    int t = threadIdx.x;
    if ((t & 31) == 0) red[t >> 5] = v;
    __syncthreads();
    float s = 0.f;
    if (t == 0) {
#pragma unroll
        for (int i = 0; i < K3_TPB / 32; i++) s += red[i];
    }
    return s;          // valid on t==0 only
}

// ---------------- K1: gate statistics (smem-reduced; inline softmax) -----------
__global__ void __launch_bounds__(K1_TPB) k1_stats(
    const float* __restrict__ Z_i, const float* __restrict__ Z_j,
    const float* __restrict__ Gate,
    const int* __restrict__ si, const int* __restrict__ sj)
{
    __shared__ float sT[KDIM][KDIM + 1];   // +1 pad: rows start at rotating banks
    __shared__ float ss[KDIM];

    const int tid = threadIdx.x;
    const int lane = tid & 31;
    const int gwarp = (blockIdx.x * K1_TPB + tid) >> 5;
    const int nwarps = (K1_BLOCKS * K1_TPB) >> 5;   // 1024 warps -> ~4.9 samples each

    // zero shared accumulators
    for (int e = tid; e < KDIM * (KDIM + 1); e += K1_TPB)
        (&sT[0][0])[e] = 0.f;
    if (tid < KDIM) ss[tid] = 0.f;
    __syncthreads();

    float sacc = 0.f;
    float tacc[KDIM];
#pragma unroll
    for (int a = 0; a < KDIM; a++) tacc[a] = 0.f;

    for (int m = gwarp; m < M_I + M_J; m += nwarps) {
        int idx; const float* Zsrc; int n;
        if (m < M_I) { idx = si[m]; Zsrc = Z_i; n = N_I; }
        else         { idx = sj[m - M_I]; Zsrc = Z_j; n = N_J; }
        float gt = Gate[idx * KDIM + lane];  // issue early (independent of reductions)
        // inline softmax over the k axis for this column
        float zv = Zsrc[lane * n + idx];
        float mx = zv;
#pragma unroll
        for (int o = 16; o; o >>= 1) mx = fmaxf(mx, __shfl_xor_sync(0xffffffffu, mx, o));
        float e = __expf(zv - mx);
        float es = e;
#pragma unroll
        for (int o = 16; o; o >>= 1) es += __shfl_xor_sync(0xffffffffu, es, o);
        float z = e / es;

        float g = 1.f / (1.f + __expf(-gt));   // faithful: j-side indexes Gate w/o offset
        float w = z * g;
        sacc += w;
#pragma unroll
        for (int a = 0; a < KDIM; a++) {
            float za = __shfl_sync(0xffffffffu, z, a);
            tacc[a] = fmaf(za, w, tacc[a]);
        }
    }

    // per-block reduction in shared (cheap ATOMS, banks parallel)
    atomicAdd(&ss[lane], sacc);
#pragma unroll
    for (int a = 0; a < KDIM; a++) atomicAdd(&sT[a][lane], tacc[a]);
    __syncthreads();

    // one flush per block to global
    for (int e = tid; e < KDIM * KDIM; e += K1_TPB)
        atomicAdd(&g_T[e], sT[e >> 5][e & 31]);
    if (tid < KDIM) atomicAdd(&g_s[tid], ss[tid]);
}

// ---------------- K2: AZC (redundant per block) + latent rows (inline softmax) -
__global__ void __launch_bounds__(K2_TPB) k2_latent(
    const float* __restrict__ A,
    const float* __restrict__ Z_i, const float* __restrict__ Z_j)
{
    __shared__ float az[DDIM][KDIM];
    const int tid = threadIdx.x;

    for (int e = tid; e < DDIM * KDIM; e += K2_TPB) {
        int dd = e >> 5, b = e & 31;
        float acc = 0.f;
#pragma unroll
        for (int a = 0; a < KDIM; a++) acc = fmaf(A[dd * KDIM + a], g_T[a * KDIM + b], acc);
        az[dd][b] = acc / g_s[b];
    }
    __syncthreads();

    int c = blockIdx.x * K2_TPB + tid;
    if (c >= N_I + N_J) return;
    const float* Zsrc; float* X; float* q; int n, cc, side;
    if (c < N_I) { Zsrc = Z_i; X = g_Xi; q = g_qi; n = N_I; cc = c; side = 0; }
    else         { Zsrc = Z_j; X = g_Xj; q = g_qj; n = N_J; cc = c - N_I; side = 1; }

    // inline column softmax (register-local)
    float v[KDIM];
    float mx = -1e30f;
#pragma unroll
    for (int a = 0; a < KDIM; a++) { v[a] = Zsrc[a * n + cc]; mx = fmaxf(mx, v[a]); }
    float sum = 0.f;
#pragma unroll
    for (int a = 0; a < KDIM; a++) { v[a] = __expf(v[a] - mx); sum += v[a]; }
    float inv = 1.f / sum;

    float x[DDIM];
#pragma unroll
    for (int dd = 0; dd < DDIM; dd++) x[dd] = 0.f;
#pragma unroll
    for (int a = 0; a < KDIM; a++) {
        float z = v[a] * inv;
#pragma unroll
        for (int dd = 0; dd < DDIM; dd++) x[dd] = fmaf(az[dd][a], z, x[dd]);
    }
    float s2 = 0.f, s1 = 0.f;
    float4* o4 = (float4*)&X[cc * DDIM];
#pragma unroll
    for (int w = 0; w < DDIM / 4; w++) {
        float4 v4 = make_float4(x[4 * w], x[4 * w + 1], x[4 * w + 2], x[4 * w + 3]);
        s2 = fmaf(v4.x, v4.x, fmaf(v4.y, v4.y, fmaf(v4.z, v4.z, fmaf(v4.w, v4.w, s2))));
        s1 += v4.x + v4.y + v4.z + v4.w;
        o4[w] = v4;
    }
    q[cc] = side == 0 ? (s2 + 2.f * EPSV * s1) : (s2 - 2.f * EPSV * s1);
}

// ---------------- K3: pair tiles + edge chunks (item loop) --------------------
__global__ void __launch_bounds__(K3_TPB, 2) k3_pair_edges(
    const float* __restrict__ beta, const float* __restrict__ gamma,
    const int* __restrict__ si, const int* __restrict__ sj,
    const int* __restrict__ spi, const int* __restrict__ spj,
    float* __restrict__ out)
{
    __shared__ float s_As[KDIM][BT + 4];   // 528B row base stays 16B aligned
    __shared__ float s_Bs[KDIM][BT + 4];
    __shared__ float s_qa[BT], s_ba[BT], s_qb[BT], s_gb[BT];
    __shared__ float s_red[K3_TPB / 32];

    const int tid = threadIdx.x;

    for (int item = blockIdx.x; item < NITEMS; item += K3_GRID) {
        __syncthreads();   // protect smem reuse across item iterations
        if (item < NPAIR) {
            // ---- dense pairwise exp-distance tile (BT x BT) ----
            int ti = item / NTJ, tj = item - ti * NTJ;
            int i0 = ti * BT, j0 = tj * BT;

            for (int e = tid; e < BT * KDIM; e += K3_TPB) {
                int r = e >> 5, kk = e & 31;       // lanes sweep kk -> coalesced row reads
                int rg = i0 + r;
                float v = 0.f;
                if (rg < M_I) v = g_Xi[si[rg] * DDIM + kk];
                s_As[kk][r] = v;
                rg = j0 + r;
                v = 0.f;
                if (rg < M_J) v = g_Xj[sj[rg] * DDIM + kk];
                s_Bs[kk][r] = v;
            }
            if (tid < BT) {
                int rg = i0 + tid;
                if (rg < M_I) { int idx = si[rg]; s_qa[tid] = g_qi[idx]; s_ba[tid] = beta[idx]; }
                else          { s_qa[tid] = 1e30f; s_ba[tid] = 0.f; }
            } else {
                int p = tid - BT;
                int rg = j0 + p;
                if (rg < M_J) { int idx = sj[rg]; s_qb[p] = g_qj[idx]; s_gb[p] = gamma[idx]; }
                else          { s_qb[p] = 1e30f; s_gb[p] = 0.f; }
            }
            __syncthreads();

            const int tx = tid & 15, ty = tid >> 4;
            const int r0 = ty * 8, c0 = tx * 8;

            unsigned long long acc[8][4];
#pragma unroll
            for (int r = 0; r < 8; r++)
#pragma unroll
                for (int c = 0; c < 4; c++) acc[r][c] = 0ULL;

#pragma unroll
            for (int kk = 0; kk < KDIM; kk++) {
                float4 a0 = *(const float4*)&s_As[kk][r0];
                float4 a1 = *(const float4*)&s_As[kk][r0 + 4];
                ulonglong2 b0 = *(const ulonglong2*)&s_Bs[kk][c0];
                ulonglong2 b1 = *(const ulonglong2*)&s_Bs[kk][c0 + 4];
                float av[8] = {a0.x, a0.y, a0.z, a0.w, a1.x, a1.y, a1.z, a1.w};
                unsigned long long bp[4] = {b0.x, b0.y, b1.x, b1.y};
#pragma unroll
                for (int r = 0; r < 8; r++) {
                    unsigned long long ad;
                    asm("mov.b64 %0, {%1, %1};" : "=l"(ad) : "f"(av[r]));
#pragma unroll
                    for (int c = 0; c < 4; c++) {
                        asm("fma.rn.f32x2 %0, %1, %2, %0;"
                            : "+l"(acc[r][c]) : "l"(ad), "l"(bp[c]));
                    }
                }
            }

            float sum = 0.f;
#pragma unroll
            for (int r = 0; r < 8; r++) {
                float qa = s_qa[r0 + r];
                float ba = s_ba[r0 + r];
#pragma unroll
                for (int c = 0; c < 4; c++) {
                    float dlo, dhi;
                    asm("mov.b64 {%0, %1}, %2;" : "=f"(dlo), "=f"(dhi) : "l"(acc[r][c]));
                    int cl = c0 + 2 * c;
                    float d2a = qa + s_qb[cl] - 2.f * dlo + C0;
                    float d2b = qa + s_qb[cl + 1] - 2.f * dhi + C0;
                    d2a = fmaxf(d2a, 0.f);
                    d2b = fmaxf(d2b, 0.f);
                    sum += __expf(ba + s_gb[cl] - sqrtf(d2a));
                    sum += __expf(ba + s_gb[cl + 1] - sqrtf(d2b));
                }
            }
            float bs = block_reduce(sum, s_red);
            if (tid == 0) atomicAdd(&g_mat, (double)bs);
        } else {
            // ---- sparse edge chunk ----
            int base = (item - NPAIR) * EDGE_PER_BLK;
            float sum = 0.f;
#pragma unroll
            for (int l = 0; l < EDGE_PER_BLK / K3_TPB; l++) {
                int e = base + l * K3_TPB + tid;
                if (e < N_EDGES) {
                    int ii = spi[e];
                    int jj = spj[e];
                    const float4* xa = (const float4*)&g_Xi[ii * DDIM];
                    const float4* xb = (const float4*)&g_Xj[jj * DDIM];
                    float dot = 0.f;
#pragma unroll
                    for (int w = 0; w < DDIM / 4; w++) {
                        float4 a = xa[w], b = xb[w];
                        dot = fmaf(a.x, b.x, dot);
                        dot = fmaf(a.y, b.y, dot);
                        dot = fmaf(a.z, b.z, dot);
                        dot = fmaf(a.w, b.w, dot);
                    }
                    float d2 = g_qi[ii] + g_qj[jj] - 2.f * dot + C0;
                    d2 = fmaxf(d2, 0.f);
                    sum += beta[ii] + gamma[jj] - sqrtf(d2);
                }
            }
            float bs = block_reduce(sum, s_red);
            if (tid == 0) atomicAdd(&g_links, (double)bs);
        }
    }

    // ---- last-block-done: final scalar + reset accumulators for next replay ----
    __syncthreads();
    __threadfence();
    __shared__ unsigned int s_last;
    if (tid == 0) s_last = atomicAdd(&g_done, 1u);
    __syncthreads();
    if (s_last == K3_GRID - 1) {
        if (tid == 0) {
            double m = atomicAdd(&g_mat, 0.0);      // read after fence chain
            double l = atomicAdd(&g_links, 0.0);
            out[0] = (float)(l - m);
            g_mat = 0.0;
            g_links = 0.0;
            g_done = 0u;
            g_s[0] = 0.f;
        }
        // re-zero stats accumulators so next replay starts clean
        for (int e = tid; e < KDIM * KDIM; e += K3_TPB) g_T[e] = 0.f;
        if (tid > 0 && tid < KDIM) g_s[tid] = 0.f;
    }
}

// ---------------- launcher -----------------------------------------------------
extern "C" void kernel_launch(void* const* d_in, const int* in_sizes, int n_in,
                              void* d_out, int out_size) {
    const float* beta  = (const float*)d_in[0];
    const float* gamma = (const float*)d_in[1];
    const float* A     = (const float*)d_in[2];
    const float* Z_i   = (const float*)d_in[3];
    const float* Z_j   = (const float*)d_in[4];
    const float* Gate  = (const float*)d_in[5];
    const int* si      = (const int*)d_in[6];
    const int* sj      = (const int*)d_in[7];
    const int* spi     = (const int*)d_in[8];
    const int* spj     = (const int*)d_in[9];
    float* out = (float*)d_out;

    k1_stats<<<K1_BLOCKS, K1_TPB>>>(Z_i, Z_j, Gate, si, sj);
    k2_latent<<<K2_BLOCKS, K2_TPB>>>(A, Z_i, Z_j);
    k3_pair_edges<<<K3_GRID, K3_TPB>>>(beta, gamma, si, sj, spi, spj, out);
}